// round 9
// baseline (speedup 1.0000x reference)
#include <cuda_runtime.h>
#include <cuda_fp16.h>
#include <math.h>

#define N_NODES 8192
#define F_IN    256
#define F_OUT   128
#define MAXNBR  512    // max row degree ~125 (binomial 8192 @ 1%); big margin

// Scratch (device globals — allocation-free per harness rules)
__device__ __half g_xph[N_NODES * F_OUT];   // 2 MB, x @ W + b in fp16 (gather source)
__device__ float  g_ssrc[N_NODES];
__device__ float  g_sdst[N_NODES];

// ---------------------------------------------------------------------------
// f32x2 packed FMA (Blackwell FFMA2 — 2x fp32 FMA throughput)
// ---------------------------------------------------------------------------
__device__ __forceinline__ unsigned long long pack2(float a, float b) {
    unsigned long long r;
    asm("mov.b64 %0, {%1, %2};" : "=l"(r) : "f"(a), "f"(b));
    return r;
}
__device__ __forceinline__ unsigned long long fma2(
    unsigned long long a, unsigned long long b, unsigned long long c) {
    unsigned long long d;
    asm("fma.rn.f32x2 %0, %1, %2, %3;" : "=l"(d) : "l"(a), "l"(b), "l"(c));
    return d;
}
__device__ __forceinline__ void unpack2(unsigned long long v, float& a, float& b) {
    asm("mov.b64 {%0, %1}, %2;" : "=f"(a), "=f"(b) : "l"(v));
}

// ---------------------------------------------------------------------------
// mbarrier + bulk-async helpers
// ---------------------------------------------------------------------------
__device__ __forceinline__ unsigned smem_u32(const void* p) {
    return (unsigned)__cvta_generic_to_shared(p);
}
__device__ __forceinline__ void mbar_init(unsigned bar, unsigned count) {
    asm volatile("mbarrier.init.shared.b64 [%0], %1;" :: "r"(bar), "r"(count) : "memory");
}
__device__ __forceinline__ void mbar_expect_tx(unsigned bar, unsigned bytes) {
    asm volatile("mbarrier.arrive.expect_tx.shared.b64 _, [%0], %1;"
                 :: "r"(bar), "r"(bytes) : "memory");
}
__device__ __forceinline__ void bulk_g2s(unsigned dst, const void* src,
                                         unsigned bytes, unsigned bar) {
    asm volatile(
        "cp.async.bulk.shared::cluster.global.mbarrier::complete_tx::bytes "
        "[%0], [%1], %2, [%3];"
        :: "r"(dst), "l"(src), "r"(bytes), "r"(bar) : "memory");
}
__device__ __forceinline__ void mbar_wait(unsigned bar, unsigned parity) {
    unsigned done;
    asm volatile(
        "{\n\t.reg .pred p;\n\t"
        "mbarrier.try_wait.parity.acquire.cta.shared::cta.b64 p, [%1], %2;\n\t"
        "selp.b32 %0, 1, 0, p;\n\t}"
        : "=r"(done) : "r"(bar), "r"(parity) : "memory");
    if (!done) {
        asm volatile(
            "{\n\t.reg .pred P1;\n\t"
            "WL_%=:\n\t"
            "mbarrier.try_wait.parity.acquire.cta.shared::cta.b64 P1, [%0], %1, 0x989680;\n\t"
            "@P1 bra.uni WD_%=;\n\t"
            "bra.uni WL_%=;\n\t"
            "WD_%=:\n\t}"
            :: "r"(bar), "r"(parity) : "memory");
    }
}

// ---------------------------------------------------------------------------
// Kernel 1: x_prime = x @ W + bias, fused with s_src/s_dst = x_prime . phi.
// Round-4 structure (proven ~20us): 64x128 tile, 256 threads, 8x4 outputs
// per thread as 16 f32x2 accumulators. x-pairs come straight out of
// ulonglong2 LDS of the transposed xs tile (rows adjacent => no packing);
// only w needs 8 duplicate-pack MOVs per k.
// ---------------------------------------------------------------------------
#define BM 64
#define BK 32
#define XS_LD 68   // padded row (floats); 272B rows keep 16B alignment

__global__ void __launch_bounds__(256) gemm_xp_kernel(
    const float* __restrict__ x, const float* __restrict__ w,
    const float* __restrict__ bias, const float* __restrict__ phi)
{
    __shared__ float xs[BK][XS_LD];   // transposed: xs[k][m]
    __shared__ float ws[BK][F_OUT];   // ws[k][n]

    const int tid  = threadIdx.x;
    const int tx   = tid & 31;   // col group: cols tx*4 .. tx*4+3
    const int ty   = tid >> 5;   // row group: rows ty*8 .. ty*8+7
    const int row0 = blockIdx.x * BM;

    unsigned long long acc[4][4];  // [row-pair p][col j]
    #pragma unroll
    for (int p = 0; p < 4; p++)
        #pragma unroll
        for (int j = 0; j < 4; j++) acc[p][j] = 0ull;

    for (int kt = 0; kt < F_IN; kt += BK) {
        // x chunk [64 rows x 32 k] -> transposed xs[k][r]
        #pragma unroll
        for (int i = 0; i < 2; i++) {
            const int l = tid + i * 256, r = l >> 3, c4 = l & 7;
            const float4 v = *(const float4*)(x + (size_t)(row0 + r) * F_IN + kt + c4 * 4);
            xs[c4 * 4 + 0][r] = v.x;
            xs[c4 * 4 + 1][r] = v.y;
            xs[c4 * 4 + 2][r] = v.z;
            xs[c4 * 4 + 3][r] = v.w;
        }
        // w chunk [32 k x 128 n], contiguous
        #pragma unroll
        for (int i = 0; i < 4; i++)
            ((float4*)ws)[tid + i * 256] =
                ((const float4*)(w + (size_t)kt * F_OUT))[tid + i * 256];
        __syncthreads();

        #pragma unroll 8
        for (int k = 0; k < BK; k++) {
            const ulonglong2 xa = *(const ulonglong2*)&xs[k][ty * 8];      // rows (0,1),(2,3)
            const ulonglong2 xb = *(const ulonglong2*)&xs[k][ty * 8 + 4];  // rows (4,5),(6,7)
            const float4 wv = *(const float4*)&ws[k][tx * 4];
            const unsigned long long xu[4] = {xa.x, xa.y, xb.x, xb.y};
            unsigned long long w2[4];
            w2[0] = pack2(wv.x, wv.x);
            w2[1] = pack2(wv.y, wv.y);
            w2[2] = pack2(wv.z, wv.z);
            w2[3] = pack2(wv.w, wv.w);
            #pragma unroll
            for (int p = 0; p < 4; p++)
                #pragma unroll
                for (int j = 0; j < 4; j++)
                    acc[p][j] = fma2(xu[p], w2[j], acc[p][j]);
        }
        __syncthreads();
    }

    // ---- epilogue: bias, fp16 store, fused score reductions ----
    float bch[4], phs[4], phd[4];
    #pragma unroll
    for (int j = 0; j < 4; j++) {
        const int c = tx * 4 + j;
        bch[j] = bias[c];
        phs[j] = phi[c];
        phd[j] = phi[F_OUT + c];
    }

    #pragma unroll
    for (int p = 0; p < 4; p++) {
        float v0[4], v1[4];
        #pragma unroll
        for (int j = 0; j < 4; j++) {
            unpack2(acc[p][j], v0[j], v1[j]);
            v0[j] += bch[j];
            v1[j] += bch[j];
        }
        #pragma unroll
        for (int e = 0; e < 2; e++) {
            const float* v = e ? v1 : v0;
            const int row = row0 + ty * 8 + 2 * p + e;
            __half2 h01 = __floats2half2_rn(v[0], v[1]);
            __half2 h23 = __floats2half2_rn(v[2], v[3]);
            uint2 st;
            st.x = reinterpret_cast<unsigned&>(h01);
            st.y = reinterpret_cast<unsigned&>(h23);
            *(uint2*)(g_xph + (size_t)row * F_OUT + tx * 4) = st;

            float ps = v[0] * phs[0] + v[1] * phs[1] + v[2] * phs[2] + v[3] * phs[3];
            float pd = v[0] * phd[0] + v[1] * phd[1] + v[2] * phd[2] + v[3] * phd[3];
            #pragma unroll
            for (int off = 16; off; off >>= 1) {
                ps += __shfl_xor_sync(0xffffffffu, ps, off);
                pd += __shfl_xor_sync(0xffffffffu, pd, off);
            }
            if (tx == 0) { g_ssrc[row] = ps; g_sdst[row] = pd; }
        }
    }
}

// ---------------------------------------------------------------------------
// Kernel 2: per-row attention. One CTA (256 thr) per row.
//  Adj row (32KB) brought in with TWO 16KB cp.async.bulk (TMA/UBLKCP) copies
//  — bypasses the per-SM LDG issue ceiling (~4.5TB/s) that capped R5, rides
//  the ~12TB/s LTS path instead. Threads scan SMEM with conflict-free
//  LDS.128 and integer nonzero tests; compaction stores (j, exp(lrelu(s)))
//  directly (no-max softmax is exact: |s| << 88, softmax shift-invariant).
//  One sum reduction; fp16 gather of x' rows (L2-resident); fold 1/sum into
//  the final float4 store.
// ---------------------------------------------------------------------------
#define CHUNK4 1024   // uint4 per 16KB chunk

__global__ void __launch_bounds__(256) gat_row_kernel(
    const float* __restrict__ adj, float* __restrict__ out)
{
    __shared__ alignas(128) uint4 s_adj[2][CHUNK4];    // 32 KB
    __shared__ float2 s_pair[MAXNBR];                  // 4 KB: {bits(j), w}
    __shared__ float4 s_acc[256];                      // 4 KB
    __shared__ float  s_w[12];
    __shared__ int    s_cnt;
    __shared__ alignas(8) unsigned long long s_bar[2];

    const int row  = blockIdx.x;
    const int tid  = threadIdx.x;
    const int lane = tid & 31;
    const int wid  = tid >> 5;

    const float s_i = g_ssrc[row];
    const unsigned bar0 = smem_u32(&s_bar[0]);
    const unsigned bar1 = smem_u32(&s_bar[1]);

    if (tid == 0) {
        s_cnt = 0;
        mbar_init(bar0, 1);
        mbar_init(bar1, 1);
    }
    __syncthreads();

    if (tid == 0) {
        const char* src = (const char*)(adj + (size_t)row * N_NODES);
        mbar_expect_tx(bar0, 16384);
        bulk_g2s(smem_u32(&s_adj[0][0]), src, 16384, bar0);
        mbar_expect_tx(bar1, 16384);
        bulk_g2s(smem_u32(&s_adj[1][0]), src + 16384, 16384, bar1);

        // self-loop: always in the mask (adj + eye > 0), pushed exactly once
        float s = s_i + g_sdst[row];
        s = fmaxf(s, 0.2f * s);
        s_pair[atomicAdd(&s_cnt, 1)] = make_float2(__int_as_float(row), __expf(s));
    }

    const int row_g = row >> 2;   // uint4 index containing the diagonal

    // ---- scan + compact, two staged chunks ----
    #pragma unroll
    for (int st = 0; st < 2; st++) {
        mbar_wait(st ? bar1 : bar0, 0);
        #pragma unroll
        for (int it = 0; it < 4; it++) {
            const int idx = tid + it * 256;         // uint4 index within chunk
            uint4 u = s_adj[st][idx];
            const int g4 = (st << 10) + idx;        // global uint4 index
            if (g4 == row_g) {                      // rare: zero self lane
                const int r3 = row & 3;
                u.x = (r3 == 0) ? 0u : u.x;
                u.y = (r3 == 1) ? 0u : u.y;
                u.z = (r3 == 2) ? 0u : u.z;
                u.w = (r3 == 3) ? 0u : u.w;
            }
            if (u.x | u.y | u.z | u.w) {
                const int jb = g4 * 4;
                #pragma unroll
                for (int c = 0; c < 4; c++) {
                    const unsigned bits = (c == 0) ? u.x : (c == 1) ? u.y
                                        : (c == 2) ? u.z : u.w;
                    if (bits) {
                        const int p = atomicAdd(&s_cnt, 1);
                        if (p < MAXNBR) {
                            const int j = jb + c;
                            float s = s_i + g_sdst[j];
                            s = fmaxf(s, 0.2f * s);
                            s_pair[p] = make_float2(__int_as_float(j), __expf(s));
                        }
                    }
                }
            }
        }
    }
    __syncthreads();
    const int cnt = min(s_cnt, MAXNBR);

    // ---- denominator: sum of weights ----
    float sm = 0.0f;
    for (int k = tid; k < cnt; k += 256) sm += s_pair[k].y;
    #pragma unroll
    for (int off = 16; off; off >>= 1)
        sm += __shfl_xor_sync(0xffffffffu, sm, off);
    if (lane == 0) s_w[wid] = sm;
    __syncthreads();
    if (tid == 0) {
        float s = 0.0f;
        #pragma unroll
        for (int i = 0; i < 8; i++) s += s_w[i];
        s_w[8] = 1.0f / s;    // >= 1 term always (self-loop)
    }
    __syncthreads();
    const float inv = s_w[8];

    // ---- fp16 weighted gather: 8 ways x 32 lanes (4 halves each) ----
    const int way = tid >> 5;                    // neighbor way 0..7
    const uint2* xp2 = (const uint2*)g_xph;      // 32 uint2 per row
    float4 acc = make_float4(0.f, 0.f, 0.f, 0.f);

    int k = way;
    for (; k + 8 < cnt; k += 16) {
        const float2 p0 = s_pair[k];
        const float2 p1 = s_pair[k + 8];
        const uint2 v0 = xp2[(size_t)__float_as_int(p0.x) * 32 + lane];
        const uint2 v1 = xp2[(size_t)__float_as_int(p1.x) * 32 + lane];
        const float2 a0 = __half22float2(*(const __half2*)&v0.x);
        const float2 b0 = __half22float2(*(const __half2*)&v0.y);
        const float2 a1 = __half22float2(*(const __half2*)&v1.x);
        const float2 b1 = __half22float2(*(const __half2*)&v1.y);
        acc.x = fmaf(p0.y, a0.x, acc.x); acc.y = fmaf(p0.y, a0.y, acc.y);
        acc.z = fmaf(p0.y, b0.x, acc.z); acc.w = fmaf(p0.y, b0.y, acc.w);
        acc.x = fmaf(p1.y, a1.x, acc.x); acc.y = fmaf(p1.y, a1.y, acc.y);
        acc.z = fmaf(p1.y, b1.x, acc.z); acc.w = fmaf(p1.y, b1.y, acc.w);
    }
    for (; k < cnt; k += 8) {
        const float2 p0 = s_pair[k];
        const uint2 v0 = xp2[(size_t)__float_as_int(p0.x) * 32 + lane];
        const float2 a0 = __half22float2(*(const __half2*)&v0.x);
        const float2 b0 = __half22float2(*(const __half2*)&v0.y);
        acc.x = fmaf(p0.y, a0.x, acc.x); acc.y = fmaf(p0.y, a0.y, acc.y);
        acc.z = fmaf(p0.y, b0.x, acc.z); acc.w = fmaf(p0.y, b0.y, acc.w);
    }
    s_acc[tid] = acc;
    __syncthreads();

    // cross-way reduction tree
    if (tid < 128) {
        const float4 o = s_acc[tid + 128];
        acc = s_acc[tid];
        acc.x += o.x; acc.y += o.y; acc.z += o.z; acc.w += o.w;
        s_acc[tid] = acc;
    }
    __syncthreads();
    if (tid < 64) {
        const float4 o = s_acc[tid + 64];
        acc = s_acc[tid];
        acc.x += o.x; acc.y += o.y; acc.z += o.z; acc.w += o.w;
        s_acc[tid] = acc;
    }
    __syncthreads();
    if (tid < 32) {
        const float4 a = s_acc[tid];
        const float4 b = s_acc[tid + 32];
        float4 r;
        r.x = (a.x + b.x) * inv;
        r.y = (a.y + b.y) * inv;
        r.z = (a.z + b.z) * inv;
        r.w = (a.w + b.w) * inv;
        *(float4*)(out + (size_t)row * F_OUT + tid * 4) = r;
    }
}

// ---------------------------------------------------------------------------
extern "C" void kernel_launch(void* const* d_in, const int* in_sizes, int n_in,
                              void* d_out, int out_size)
{
    const float* adj  = (const float*)d_in[0];   // [8192, 8192]
    const float* x    = (const float*)d_in[1];   // [8192, 256]
    const float* w    = (const float*)d_in[2];   // [256, 128]
    const float* bias = (const float*)d_in[3];   // [128]
    const float* phi  = (const float*)d_in[4];   // [256, 1]
    float* out = (float*)d_out;                  // [8192, 128]

    gemm_xp_kernel<<<N_NODES / BM, 256>>>(x, w, bias, phi);
    gat_row_kernel<<<N_NODES, 256>>>(adj, out);
}

// round 10
// speedup vs baseline: 1.1177x; 1.1177x over previous
#include <cuda_runtime.h>
#include <cuda_fp16.h>
#include <math.h>

#define N_NODES 8192
#define F_IN    256
#define F_OUT   128
#define MAXDEG  256    // row degree ~ Binom(8192,1%): mean 82, sd 9; 256 = 19 sigma

// Scratch (device globals — allocation-free per harness rules)
__device__ __half g_xph[N_NODES * F_OUT];     // 2 MB fp16 x' (gather source)
__device__ float  g_ssrc[N_NODES];
__device__ float  g_sdst[N_NODES];
__device__ int    g_cnt[N_NODES];             // per-row neighbor counts
__device__ int    g_nbr[N_NODES * MAXDEG];    // 8 MB compacted neighbor lists

// ---------------------------------------------------------------------------
// f32x2 packed FMA (Blackwell FFMA2 — 2x fp32 FMA throughput)
// ---------------------------------------------------------------------------
__device__ __forceinline__ unsigned long long pack2(float a, float b) {
    unsigned long long r;
    asm("mov.b64 %0, {%1, %2};" : "=l"(r) : "f"(a), "f"(b));
    return r;
}
__device__ __forceinline__ unsigned long long fma2(
    unsigned long long a, unsigned long long b, unsigned long long c) {
    unsigned long long d;
    asm("fma.rn.f32x2 %0, %1, %2, %3;" : "=l"(d) : "l"(a), "l"(b), "l"(c));
    return d;
}
__device__ __forceinline__ void unpack2(unsigned long long v, float& a, float& b) {
    asm("mov.b64 {%0, %1}, %2;" : "=f"(a), "=f"(b) : "l"(v));
}

// ---------------------------------------------------------------------------
// Kernel 1: x' = x @ W + bias, fused scores s_src/s_dst = x' . phi.
// (Measured ~20us.) Also zeroes g_cnt for the compaction kernel that follows.
// ---------------------------------------------------------------------------
#define BM 64
#define BK 32
#define XS_LD 68

__global__ void __launch_bounds__(256) gemm_xp_kernel(
    const float* __restrict__ x, const float* __restrict__ w,
    const float* __restrict__ bias, const float* __restrict__ phi)
{
    __shared__ float xs[BK][XS_LD];   // transposed: xs[k][m]
    __shared__ float ws[BK][F_OUT];   // ws[k][n]

    const int tid  = threadIdx.x;
    const int tx   = tid & 31;
    const int ty   = tid >> 5;
    const int row0 = blockIdx.x * BM;

    // zero the per-row counters (completes before convert kernel launches)
    const int gt = blockIdx.x * 256 + tid;
    if (gt < N_NODES) g_cnt[gt] = 0;

    unsigned long long acc[4][4];
    #pragma unroll
    for (int p = 0; p < 4; p++)
        #pragma unroll
        for (int j = 0; j < 4; j++) acc[p][j] = 0ull;

    for (int kt = 0; kt < F_IN; kt += BK) {
        #pragma unroll
        for (int i = 0; i < 2; i++) {
            const int l = tid + i * 256, r = l >> 3, c4 = l & 7;
            const float4 v = *(const float4*)(x + (size_t)(row0 + r) * F_IN + kt + c4 * 4);
            xs[c4 * 4 + 0][r] = v.x;
            xs[c4 * 4 + 1][r] = v.y;
            xs[c4 * 4 + 2][r] = v.z;
            xs[c4 * 4 + 3][r] = v.w;
        }
        #pragma unroll
        for (int i = 0; i < 4; i++)
            ((float4*)ws)[tid + i * 256] =
                ((const float4*)(w + (size_t)kt * F_OUT))[tid + i * 256];
        __syncthreads();

        #pragma unroll 8
        for (int k = 0; k < BK; k++) {
            const ulonglong2 xa = *(const ulonglong2*)&xs[k][ty * 8];
            const ulonglong2 xb = *(const ulonglong2*)&xs[k][ty * 8 + 4];
            const float4 wv = *(const float4*)&ws[k][tx * 4];
            const unsigned long long xu[4] = {xa.x, xa.y, xb.x, xb.y};
            unsigned long long w2[4];
            w2[0] = pack2(wv.x, wv.x);
            w2[1] = pack2(wv.y, wv.y);
            w2[2] = pack2(wv.z, wv.z);
            w2[3] = pack2(wv.w, wv.w);
            #pragma unroll
            for (int p = 0; p < 4; p++)
                #pragma unroll
                for (int j = 0; j < 4; j++)
                    acc[p][j] = fma2(xu[p], w2[j], acc[p][j]);
        }
        __syncthreads();
    }

    float bch[4], phs[4], phd[4];
    #pragma unroll
    for (int j = 0; j < 4; j++) {
        const int c = tx * 4 + j;
        bch[j] = bias[c];
        phs[j] = phi[c];
        phd[j] = phi[F_OUT + c];
    }

    #pragma unroll
    for (int p = 0; p < 4; p++) {
        float v0[4], v1[4];
        #pragma unroll
        for (int j = 0; j < 4; j++) {
            unpack2(acc[p][j], v0[j], v1[j]);
            v0[j] += bch[j];
            v1[j] += bch[j];
        }
        #pragma unroll
        for (int e = 0; e < 2; e++) {
            const float* v = e ? v1 : v0;
            const int row = row0 + ty * 8 + 2 * p + e;
            __half2 h01 = __floats2half2_rn(v[0], v[1]);
            __half2 h23 = __floats2half2_rn(v[2], v[3]);
            uint2 st;
            st.x = reinterpret_cast<unsigned&>(h01);
            st.y = reinterpret_cast<unsigned&>(h23);
            *(uint2*)(g_xph + (size_t)row * F_OUT + tx * 4) = st;

            float ps = v[0] * phs[0] + v[1] * phs[1] + v[2] * phs[2] + v[3] * phs[3];
            float pd = v[0] * phd[0] + v[1] * phd[1] + v[2] * phd[2] + v[3] * phd[3];
            #pragma unroll
            for (int off = 16; off; off >>= 1) {
                ps += __shfl_xor_sync(0xffffffffu, ps, off);
                pd += __shfl_xor_sync(0xffffffffu, pd, off);
            }
            if (tx == 0) { g_ssrc[row] = ps; g_sdst[row] = pd; }
        }
    }
}

// ---------------------------------------------------------------------------
// Kernel 2: adjacency compaction — PURE DRAM STREAMER.
// One CTA per row (8 warps x 1KB segment). Per lane: 8 front-batched
// LDG.128 (.cs), then per 512B chunk: 4 integer-nonzero ballots, one
// warp-aggregated atomicAdd on the row counter, scattered index writes
// (expected 1.28 hits / chunk). Diagonal excluded here; self-loop is added
// in the attention kernel (mask = adj + eye, self counted exactly once).
// ---------------------------------------------------------------------------
__global__ void __launch_bounds__(256) adj_compact_kernel(const float* __restrict__ adj)
{
    const int row  = blockIdx.x;
    const int lane = threadIdx.x & 31;
    const int wseg = threadIdx.x >> 5;

    const uint4* arow = (const uint4*)(adj + (size_t)row * N_NODES);
    int* nbr = g_nbr + (size_t)row * MAXDEG;

    uint4 u[8];
    #pragma unroll
    for (int i = 0; i < 8; i++)
        u[i] = __ldcs(&arow[wseg * 256 + i * 32 + lane]);

    #pragma unroll
    for (int i = 0; i < 8; i++) {
        const int idx4 = wseg * 256 + i * 32 + lane;
        const int j0 = idx4 * 4;
        const bool h0 = u[i].x && (j0 + 0 != row);
        const bool h1 = u[i].y && (j0 + 1 != row);
        const bool h2 = u[i].z && (j0 + 2 != row);
        const bool h3 = u[i].w && (j0 + 3 != row);
        const unsigned b0 = __ballot_sync(0xffffffffu, h0);
        const unsigned b1 = __ballot_sync(0xffffffffu, h1);
        const unsigned b2 = __ballot_sync(0xffffffffu, h2);
        const unsigned b3 = __ballot_sync(0xffffffffu, h3);
        const int c0 = __popc(b0), c1 = __popc(b1), c2 = __popc(b2), c3 = __popc(b3);
        const int tot = c0 + c1 + c2 + c3;
        if (tot) {                              // warp-uniform (ballot-derived)
            int base = 0;
            if (lane == 0) base = atomicAdd(&g_cnt[row], tot);
            base = __shfl_sync(0xffffffffu, base, 0);
            if (base + tot <= MAXDEG) {
                const unsigned ml = (1u << lane) - 1u;
                if (h0) nbr[base + __popc(b0 & ml)] = j0;
                if (h1) nbr[base + c0 + __popc(b1 & ml)] = j0 + 1;
                if (h2) nbr[base + c0 + c1 + __popc(b2 & ml)] = j0 + 2;
                if (h3) nbr[base + c0 + c1 + c2 + __popc(b3 & ml)] = j0 + 3;
            }
        }
    }
}

// ---------------------------------------------------------------------------
// Kernel 3: attention + aggregation. ONE WARP PER ROW — zero CTA barriers,
// zero cross-warp reductions. Weights w = exp(lrelu(s_src+s_dst)) with the
// no-max softmax (exact: |s| << 88, softmax shift-invariant); one shfl sum;
// fp16 gather of x' rows from L2; lane writes its float4 of the output.
// ---------------------------------------------------------------------------
__global__ void __launch_bounds__(256) gat_warp_kernel(float* __restrict__ out)
{
    __shared__ float2 sp[8][MAXDEG];   // per-warp {bits(j), w}, 16 KB

    const int lane = threadIdx.x & 31;
    const int wid  = threadIdx.x >> 5;
    const int row  = blockIdx.x * 8 + wid;

    const float s_i = g_ssrc[row];
    const int cnt = min(g_cnt[row], MAXDEG);
    const int* nbr = g_nbr + (size_t)row * MAXDEG;

    // per-lane weight computation + partial sum
    float sum = 0.0f;
    for (int k = lane; k < cnt; k += 32) {
        const int j = nbr[k];
        float s = s_i + g_sdst[j];
        s = fmaxf(s, 0.2f * s);
        const float wv = __expf(s);
        sp[wid][k] = make_float2(__int_as_float(j), wv);
        sum += wv;
    }
    #pragma unroll
    for (int off = 16; off; off >>= 1)
        sum += __shfl_xor_sync(0xffffffffu, sum, off);

    // self-loop (always in mask, exactly once: diagonal excluded in compaction)
    float s_self = s_i + g_sdst[row];
    s_self = fmaxf(s_self, 0.2f * s_self);
    const float w_self = __expf(s_self);
    const float inv = 1.0f / (sum + w_self);
    __syncwarp();

    // gather: acc over features lane*4 .. lane*4+3
    const uint2* xp2 = (const uint2*)g_xph;   // 32 uint2 per x' row
    uint2 vs = xp2[(size_t)row * 32 + lane];
    float2 sa = __half22float2(*(const __half2*)&vs.x);
    float2 sb = __half22float2(*(const __half2*)&vs.y);
    float4 acc = make_float4(w_self * sa.x, w_self * sa.y,
                             w_self * sb.x, w_self * sb.y);

    int k = 0;
    for (; k + 4 <= cnt; k += 4) {
        const float2 p0 = sp[wid][k],     p1 = sp[wid][k + 1];
        const float2 p2 = sp[wid][k + 2], p3 = sp[wid][k + 3];
        const uint2 v0 = xp2[(size_t)__float_as_int(p0.x) * 32 + lane];
        const uint2 v1 = xp2[(size_t)__float_as_int(p1.x) * 32 + lane];
        const uint2 v2 = xp2[(size_t)__float_as_int(p2.x) * 32 + lane];
        const uint2 v3 = xp2[(size_t)__float_as_int(p3.x) * 32 + lane];
        const float2 a0 = __half22float2(*(const __half2*)&v0.x);
        const float2 b0 = __half22float2(*(const __half2*)&v0.y);
        const float2 a1 = __half22float2(*(const __half2*)&v1.x);
        const float2 b1 = __half22float2(*(const __half2*)&v1.y);
        const float2 a2 = __half22float2(*(const __half2*)&v2.x);
        const float2 b2 = __half22float2(*(const __half2*)&v2.y);
        const float2 a3 = __half22float2(*(const __half2*)&v3.x);
        const float2 b3 = __half22float2(*(const __half2*)&v3.y);
        acc.x = fmaf(p0.y, a0.x, acc.x); acc.y = fmaf(p0.y, a0.y, acc.y);
        acc.z = fmaf(p0.y, b0.x, acc.z); acc.w = fmaf(p0.y, b0.y, acc.w);
        acc.x = fmaf(p1.y, a1.x, acc.x); acc.y = fmaf(p1.y, a1.y, acc.y);
        acc.z = fmaf(p1.y, b1.x, acc.z); acc.w = fmaf(p1.y, b1.y, acc.w);
        acc.x = fmaf(p2.y, a2.x, acc.x); acc.y = fmaf(p2.y, a2.y, acc.y);
        acc.z = fmaf(p2.y, b2.x, acc.z); acc.w = fmaf(p2.y, b2.y, acc.w);
        acc.x = fmaf(p3.y, a3.x, acc.x); acc.y = fmaf(p3.y, a3.y, acc.y);
        acc.z = fmaf(p3.y, b3.x, acc.z); acc.w = fmaf(p3.y, b3.y, acc.w);
    }
    for (; k < cnt; k++) {
        const float2 p0 = sp[wid][k];
        const uint2 v0 = xp2[(size_t)__float_as_int(p0.x) * 32 + lane];
        const float2 a0 = __half22float2(*(const __half2*)&v0.x);
        const float2 b0 = __half22float2(*(const __half2*)&v0.y);
        acc.x = fmaf(p0.y, a0.x, acc.x); acc.y = fmaf(p0.y, a0.y, acc.y);
        acc.z = fmaf(p0.y, b0.x, acc.z); acc.w = fmaf(p0.y, b0.y, acc.w);
    }

    float4 r;
    r.x = acc.x * inv; r.y = acc.y * inv; r.z = acc.z * inv; r.w = acc.w * inv;
    *(float4*)(out + (size_t)row * F_OUT + lane * 4) = r;
}

// ---------------------------------------------------------------------------
extern "C" void kernel_launch(void* const* d_in, const int* in_sizes, int n_in,
                              void* d_out, int out_size)
{
    const float* adj  = (const float*)d_in[0];   // [8192, 8192]
    const float* x    = (const float*)d_in[1];   // [8192, 256]
    const float* w    = (const float*)d_in[2];   // [256, 128]
    const float* bias = (const float*)d_in[3];   // [128]
    const float* phi  = (const float*)d_in[4];   // [256, 1]
    float* out = (float*)d_out;                  // [8192, 128]

    gemm_xp_kernel<<<N_NODES / BM, 256>>>(x, w, bias, phi);   // also zeroes g_cnt
    adj_compact_kernel<<<N_NODES, 256>>>(adj);
    gat_warp_kernel<<<N_NODES / 8, 256>>>(out);
}

// round 11
// speedup vs baseline: 1.1187x; 1.0009x over previous
#include <cuda_runtime.h>
#include <cuda_fp16.h>
#include <math.h>

#define N_NODES 8192
#define F_IN    256
#define F_OUT   128
#define MAXDEG  256    // row degree ~ Binom(8192,1%): mean 82, sd 9; 256 = 19 sigma

// Scratch (device globals — allocation-free per harness rules)
__device__ __half g_xph[N_NODES * F_OUT];     // 2 MB fp16 x' (gather source)
__device__ float  g_ssrc[N_NODES];
__device__ float  g_sdst[N_NODES];
__device__ int    g_cnt[N_NODES];             // per-row neighbor counts
__device__ int    g_nbr[N_NODES * MAXDEG];    // 8 MB compacted neighbor lists

// ---------------------------------------------------------------------------
// f32x2 packed FMA (Blackwell FFMA2 — 2x fp32 FMA throughput)
// ---------------------------------------------------------------------------
__device__ __forceinline__ unsigned long long pack2(float a, float b) {
    unsigned long long r;
    asm("mov.b64 %0, {%1, %2};" : "=l"(r) : "f"(a), "f"(b));
    return r;
}
__device__ __forceinline__ unsigned long long fma2(
    unsigned long long a, unsigned long long b, unsigned long long c) {
    unsigned long long d;
    asm("fma.rn.f32x2 %0, %1, %2, %3;" : "=l"(d) : "l"(a), "l"(b), "l"(c));
    return d;
}
__device__ __forceinline__ void unpack2(unsigned long long v, float& a, float& b) {
    asm("mov.b64 {%0, %1}, %2;" : "=f"(a), "=f"(b) : "l"(v));
}

// ---------------------------------------------------------------------------
// Kernel 1: x' = x @ W + bias, fused scores s_src/s_dst = x' . phi.
// (Measured ~20us.) Also zeroes g_cnt for the compaction kernel that follows.
// ---------------------------------------------------------------------------
#define BM 64
#define BK 32
#define XS_LD 68

__global__ void __launch_bounds__(256) gemm_xp_kernel(
    const float* __restrict__ x, const float* __restrict__ w,
    const float* __restrict__ bias, const float* __restrict__ phi)
{
    __shared__ float xs[BK][XS_LD];   // transposed: xs[k][m]
    __shared__ float ws[BK][F_OUT];   // ws[k][n]

    const int tid  = threadIdx.x;
    const int tx   = tid & 31;
    const int ty   = tid >> 5;
    const int row0 = blockIdx.x * BM;

    // zero the per-row counters (completes before convert kernel launches)
    const int gt = blockIdx.x * 256 + tid;
    if (gt < N_NODES) g_cnt[gt] = 0;

    unsigned long long acc[4][4];
    #pragma unroll
    for (int p = 0; p < 4; p++)
        #pragma unroll
        for (int j = 0; j < 4; j++) acc[p][j] = 0ull;

    for (int kt = 0; kt < F_IN; kt += BK) {
        #pragma unroll
        for (int i = 0; i < 2; i++) {
            const int l = tid + i * 256, r = l >> 3, c4 = l & 7;
            const float4 v = *(const float4*)(x + (size_t)(row0 + r) * F_IN + kt + c4 * 4);
            xs[c4 * 4 + 0][r] = v.x;
            xs[c4 * 4 + 1][r] = v.y;
            xs[c4 * 4 + 2][r] = v.z;
            xs[c4 * 4 + 3][r] = v.w;
        }
        #pragma unroll
        for (int i = 0; i < 4; i++)
            ((float4*)ws)[tid + i * 256] =
                ((const float4*)(w + (size_t)kt * F_OUT))[tid + i * 256];
        __syncthreads();

        #pragma unroll 8
        for (int k = 0; k < BK; k++) {
            const ulonglong2 xa = *(const ulonglong2*)&xs[k][ty * 8];
            const ulonglong2 xb = *(const ulonglong2*)&xs[k][ty * 8 + 4];
            const float4 wv = *(const float4*)&ws[k][tx * 4];
            const unsigned long long xu[4] = {xa.x, xa.y, xb.x, xb.y};
            unsigned long long w2[4];
            w2[0] = pack2(wv.x, wv.x);
            w2[1] = pack2(wv.y, wv.y);
            w2[2] = pack2(wv.z, wv.z);
            w2[3] = pack2(wv.w, wv.w);
            #pragma unroll
            for (int p = 0; p < 4; p++)
                #pragma unroll
                for (int j = 0; j < 4; j++)
                    acc[p][j] = fma2(xu[p], w2[j], acc[p][j]);
        }
        __syncthreads();
    }

    float bch[4], phs[4], phd[4];
    #pragma unroll
    for (int j = 0; j < 4; j++) {
        const int c = tx * 4 + j;
        bch[j] = bias[c];
        phs[j] = phi[c];
        phd[j] = phi[F_OUT + c];
    }

    #pragma unroll
    for (int p = 0; p < 4; p++) {
        float v0[4], v1[4];
        #pragma unroll
        for (int j = 0; j < 4; j++) {
            unpack2(acc[p][j], v0[j], v1[j]);
            v0[j] += bch[j];
            v1[j] += bch[j];
        }
        #pragma unroll
        for (int e = 0; e < 2; e++) {
            const float* v = e ? v1 : v0;
            const int row = row0 + ty * 8 + 2 * p + e;
            __half2 h01 = __floats2half2_rn(v[0], v[1]);
            __half2 h23 = __floats2half2_rn(v[2], v[3]);
            uint2 st;
            st.x = reinterpret_cast<unsigned&>(h01);
            st.y = reinterpret_cast<unsigned&>(h23);
            *(uint2*)(g_xph + (size_t)row * F_OUT + tx * 4) = st;

            float ps = v[0] * phs[0] + v[1] * phs[1] + v[2] * phs[2] + v[3] * phs[3];
            float pd = v[0] * phd[0] + v[1] * phd[1] + v[2] * phd[2] + v[3] * phd[3];
            #pragma unroll
            for (int off = 16; off; off >>= 1) {
                ps += __shfl_xor_sync(0xffffffffu, ps, off);
                pd += __shfl_xor_sync(0xffffffffu, pd, off);
            }
            if (tx == 0) { g_ssrc[row] = ps; g_sdst[row] = pd; }
        }
    }
}

// ---------------------------------------------------------------------------
// Kernel 2: adjacency compaction — PURE DRAM STREAMER.
// One CTA per row (8 warps x 1KB segment). Per lane: 8 front-batched
// LDG.128 (.cs), then per 512B chunk: 4 integer-nonzero ballots, one
// warp-aggregated atomicAdd on the row counter, scattered index writes
// (expected 1.28 hits / chunk). Diagonal excluded here; self-loop is added
// in the attention kernel (mask = adj + eye, self counted exactly once).
// ---------------------------------------------------------------------------
__global__ void __launch_bounds__(256) adj_compact_kernel(const float* __restrict__ adj)
{
    const int row  = blockIdx.x;
    const int lane = threadIdx.x & 31;
    const int wseg = threadIdx.x >> 5;

    const uint4* arow = (const uint4*)(adj + (size_t)row * N_NODES);
    int* nbr = g_nbr + (size_t)row * MAXDEG;

    uint4 u[8];
    #pragma unroll
    for (int i = 0; i < 8; i++)
        u[i] = __ldcs(&arow[wseg * 256 + i * 32 + lane]);

    #pragma unroll
    for (int i = 0; i < 8; i++) {
        const int idx4 = wseg * 256 + i * 32 + lane;
        const int j0 = idx4 * 4;
        const bool h0 = u[i].x && (j0 + 0 != row);
        const bool h1 = u[i].y && (j0 + 1 != row);
        const bool h2 = u[i].z && (j0 + 2 != row);
        const bool h3 = u[i].w && (j0 + 3 != row);
        const unsigned b0 = __ballot_sync(0xffffffffu, h0);
        const unsigned b1 = __ballot_sync(0xffffffffu, h1);
        const unsigned b2 = __ballot_sync(0xffffffffu, h2);
        const unsigned b3 = __ballot_sync(0xffffffffu, h3);
        const int c0 = __popc(b0), c1 = __popc(b1), c2 = __popc(b2), c3 = __popc(b3);
        const int tot = c0 + c1 + c2 + c3;
        if (tot) {                              // warp-uniform (ballot-derived)
            int base = 0;
            if (lane == 0) base = atomicAdd(&g_cnt[row], tot);
            base = __shfl_sync(0xffffffffu, base, 0);
            if (base + tot <= MAXDEG) {
                const unsigned ml = (1u << lane) - 1u;
                if (h0) nbr[base + __popc(b0 & ml)] = j0;
                if (h1) nbr[base + c0 + __popc(b1 & ml)] = j0 + 1;
                if (h2) nbr[base + c0 + c1 + __popc(b2 & ml)] = j0 + 2;
                if (h3) nbr[base + c0 + c1 + c2 + __popc(b3 & ml)] = j0 + 3;
            }
        }
    }
}

// ---------------------------------------------------------------------------
// Kernel 3: attention + aggregation. ONE WARP PER ROW — zero CTA barriers,
// zero cross-warp reductions. Weights w = exp(lrelu(s_src+s_dst)) with the
// no-max softmax (exact: |s| << 88, softmax shift-invariant); one shfl sum;
// fp16 gather of x' rows from L2; lane writes its float4 of the output.
// ---------------------------------------------------------------------------
__global__ void __launch_bounds__(256) gat_warp_kernel(float* __restrict__ out)
{
    __shared__ float2 sp[8][MAXDEG];   // per-warp {bits(j), w}, 16 KB

    const int lane = threadIdx.x & 31;
    const int wid  = threadIdx.x >> 5;
    const int row  = blockIdx.x * 8 + wid;

    const float s_i = g_ssrc[row];
    const int cnt = min(g_cnt[row], MAXDEG);
    const int* nbr = g_nbr + (size_t)row * MAXDEG;

    // per-lane weight computation + partial sum
    float sum = 0.0f;
    for (int k = lane; k < cnt; k += 32) {
        const int j = nbr[k];
        float s = s_i + g_sdst[j];
        s = fmaxf(s, 0.2f * s);
        const float wv = __expf(s);
        sp[wid][k] = make_float2(__int_as_float(j), wv);
        sum += wv;
    }
    #pragma unroll
    for (int off = 16; off; off >>= 1)
        sum += __shfl_xor_sync(0xffffffffu, sum, off);

    // self-loop (always in mask, exactly once: diagonal excluded in compaction)
    float s_self = s_i + g_sdst[row];
    s_self = fmaxf(s_self, 0.2f * s_self);
    const float w_self = __expf(s_self);
    const float inv = 1.0f / (sum + w_self);
    __syncwarp();

    // gather: acc over features lane*4 .. lane*4+3
    const uint2* xp2 = (const uint2*)g_xph;   // 32 uint2 per x' row
    uint2 vs = xp2[(size_t)row * 32 + lane];
    float2 sa = __half22float2(*(const __half2*)&vs.x);
    float2 sb = __half22float2(*(const __half2*)&vs.y);
    float4 acc = make_float4(w_self * sa.x, w_self * sa.y,
                             w_self * sb.x, w_self * sb.y);

    int k = 0;
    for (; k + 4 <= cnt; k += 4) {
        const float2 p0 = sp[wid][k],     p1 = sp[wid][k + 1];
        const float2 p2 = sp[wid][k + 2], p3 = sp[wid][k + 3];
        const uint2 v0 = xp2[(size_t)__float_as_int(p0.x) * 32 + lane];
        const uint2 v1 = xp2[(size_t)__float_as_int(p1.x) * 32 + lane];
        const uint2 v2 = xp2[(size_t)__float_as_int(p2.x) * 32 + lane];
        const uint2 v3 = xp2[(size_t)__float_as_int(p3.x) * 32 + lane];
        const float2 a0 = __half22float2(*(const __half2*)&v0.x);
        const float2 b0 = __half22float2(*(const __half2*)&v0.y);
        const float2 a1 = __half22float2(*(const __half2*)&v1.x);
        const float2 b1 = __half22float2(*(const __half2*)&v1.y);
        const float2 a2 = __half22float2(*(const __half2*)&v2.x);
        const float2 b2 = __half22float2(*(const __half2*)&v2.y);
        const float2 a3 = __half22float2(*(const __half2*)&v3.x);
        const float2 b3 = __half22float2(*(const __half2*)&v3.y);
        acc.x = fmaf(p0.y, a0.x, acc.x); acc.y = fmaf(p0.y, a0.y, acc.y);
        acc.z = fmaf(p0.y, b0.x, acc.z); acc.w = fmaf(p0.y, b0.y, acc.w);
        acc.x = fmaf(p1.y, a1.x, acc.x); acc.y = fmaf(p1.y, a1.y, acc.y);
        acc.z = fmaf(p1.y, b1.x, acc.z); acc.w = fmaf(p1.y, b1.y, acc.w);
        acc.x = fmaf(p2.y, a2.x, acc.x); acc.y = fmaf(p2.y, a2.y, acc.y);
        acc.z = fmaf(p2.y, b2.x, acc.z); acc.w = fmaf(p2.y, b2.y, acc.w);
        acc.x = fmaf(p3.y, a3.x, acc.x); acc.y = fmaf(p3.y, a3.y, acc.y);
        acc.z = fmaf(p3.y, b3.x, acc.z); acc.w = fmaf(p3.y, b3.y, acc.w);
    }
    for (; k < cnt; k++) {
        const float2 p0 = sp[wid][k];
        const uint2 v0 = xp2[(size_t)__float_as_int(p0.x) * 32 + lane];
        const float2 a0 = __half22float2(*(const __half2*)&v0.x);
        const float2 b0 = __half22float2(*(const __half2*)&v0.y);
        acc.x = fmaf(p0.y, a0.x, acc.x); acc.y = fmaf(p0.y, a0.y, acc.y);
        acc.z = fmaf(p0.y, b0.x, acc.z); acc.w = fmaf(p0.y, b0.y, acc.w);
    }

    float4 r;
    r.x = acc.x * inv; r.y = acc.y * inv; r.z = acc.z * inv; r.w = acc.w * inv;
    *(float4*)(out + (size_t)row * F_OUT + lane * 4) = r;
}

// ---------------------------------------------------------------------------
extern "C" void kernel_launch(void* const* d_in, const int* in_sizes, int n_in,
                              void* d_out, int out_size)
{
    const float* adj  = (const float*)d_in[0];   // [8192, 8192]
    const float* x    = (const float*)d_in[1];   // [8192, 256]
    const float* w    = (const float*)d_in[2];   // [256, 128]
    const float* bias = (const float*)d_in[3];   // [128]
    const float* phi  = (const float*)d_in[4];   // [256, 1]
    float* out = (float*)d_out;                  // [8192, 128]

    gemm_xp_kernel<<<N_NODES / BM, 256>>>(x, w, bias, phi);   // also zeroes g_cnt
    adj_compact_kernel<<<N_NODES, 256>>>(adj);
    gat_warp_kernel<<<N_NODES / 8, 256>>>(out);
}

// round 12
// speedup vs baseline: 1.2061x; 1.0781x over previous
#include <cuda_runtime.h>
#include <cuda_fp16.h>
#include <math.h>

#define N_NODES 8192
#define F_IN    256
#define F_OUT   128
#define MAXNBR  512    // row degree ~ Binom(8192,1%): mean 82, sd 9

// Scratch (device globals — allocation-free per harness rules)
__device__ __half g_xph[N_NODES * F_OUT];   // 2 MB fp16 x' (gather source)
__device__ float  g_ssrc[N_NODES];
__device__ float  g_sdst[N_NODES];

// ---------------------------------------------------------------------------
// f32x2 packed FMA (Blackwell FFMA2 — 2x fp32 FMA throughput)
// ---------------------------------------------------------------------------
__device__ __forceinline__ unsigned long long pack2(float a, float b) {
    unsigned long long r;
    asm("mov.b64 %0, {%1, %2};" : "=l"(r) : "f"(a), "f"(b));
    return r;
}
__device__ __forceinline__ unsigned long long fma2(
    unsigned long long a, unsigned long long b, unsigned long long c) {
    unsigned long long d;
    asm("fma.rn.f32x2 %0, %1, %2, %3;" : "=l"(d) : "l"(a), "l"(b), "l"(c));
    return d;
}
__device__ __forceinline__ void unpack2(unsigned long long v, float& a, float& b) {
    asm("mov.b64 {%0, %1}, %2;" : "=f"(a), "=f"(b) : "l"(v));
}

// ---------------------------------------------------------------------------
// Kernel 1: x' = x @ W + bias, fused scores s_src/s_dst = x' . phi.
// BM=32 -> grid 256 (R11 profile showed grid=128 left 20 SMs idle, occ 12%).
// 256 threads, 4 rows x 4 cols per thread as 8 f32x2 accumulators.
// ---------------------------------------------------------------------------
#define BM 32
#define BK 32
#define XS_LD 36   // padded row (floats)

__global__ void __launch_bounds__(256) gemm_xp_kernel(
    const float* __restrict__ x, const float* __restrict__ w,
    const float* __restrict__ bias, const float* __restrict__ phi)
{
    __shared__ float xs[BK][XS_LD];   // transposed: xs[k][m]
    __shared__ float ws[BK][F_OUT];   // ws[k][n]

    const int tid  = threadIdx.x;
    const int tx   = tid & 31;   // col group: cols tx*4 .. tx*4+3
    const int ty   = tid >> 5;   // row group: rows ty*4 .. ty*4+3
    const int row0 = blockIdx.x * BM;

    unsigned long long acc[2][4];  // [row-pair p][col j]
    #pragma unroll
    for (int p = 0; p < 2; p++)
        #pragma unroll
        for (int j = 0; j < 4; j++) acc[p][j] = 0ull;

    for (int kt = 0; kt < F_IN; kt += BK) {
        // x chunk [32 rows x 32 k] -> transposed xs[k][r]; one float4/thread
        {
            const int r = tid >> 3, c4 = tid & 7;
            const float4 v = *(const float4*)(x + (size_t)(row0 + r) * F_IN + kt + c4 * 4);
            xs[c4 * 4 + 0][r] = v.x;
            xs[c4 * 4 + 1][r] = v.y;
            xs[c4 * 4 + 2][r] = v.z;
            xs[c4 * 4 + 3][r] = v.w;
        }
        // w chunk [32 k x 128 n], contiguous
        #pragma unroll
        for (int i = 0; i < 4; i++)
            ((float4*)ws)[tid + i * 256] =
                ((const float4*)(w + (size_t)kt * F_OUT))[tid + i * 256];
        __syncthreads();

        #pragma unroll 8
        for (int k = 0; k < BK; k++) {
            const ulonglong2 xa = *(const ulonglong2*)&xs[k][ty * 4]; // rows (0,1),(2,3)
            const float4 wv = *(const float4*)&ws[k][tx * 4];
            const unsigned long long xu[2] = {xa.x, xa.y};
            unsigned long long w2[4];
            w2[0] = pack2(wv.x, wv.x);
            w2[1] = pack2(wv.y, wv.y);
            w2[2] = pack2(wv.z, wv.z);
            w2[3] = pack2(wv.w, wv.w);
            #pragma unroll
            for (int p = 0; p < 2; p++)
                #pragma unroll
                for (int j = 0; j < 4; j++)
                    acc[p][j] = fma2(xu[p], w2[j], acc[p][j]);
        }
        __syncthreads();
    }

    // ---- epilogue: bias, fp16 store, fused score reductions ----
    float bch[4], phs[4], phd[4];
    #pragma unroll
    for (int j = 0; j < 4; j++) {
        const int c = tx * 4 + j;
        bch[j] = bias[c];
        phs[j] = phi[c];
        phd[j] = phi[F_OUT + c];
    }

    #pragma unroll
    for (int p = 0; p < 2; p++) {
        float v0[4], v1[4];
        #pragma unroll
        for (int j = 0; j < 4; j++) {
            unpack2(acc[p][j], v0[j], v1[j]);
            v0[j] += bch[j];
            v1[j] += bch[j];
        }
        #pragma unroll
        for (int e = 0; e < 2; e++) {
            const float* v = e ? v1 : v0;
            const int row = row0 + ty * 4 + 2 * p + e;
            __half2 h01 = __floats2half2_rn(v[0], v[1]);
            __half2 h23 = __floats2half2_rn(v[2], v[3]);
            uint2 st;
            st.x = reinterpret_cast<unsigned&>(h01);
            st.y = reinterpret_cast<unsigned&>(h23);
            *(uint2*)(g_xph + (size_t)row * F_OUT + tx * 4) = st;

            float ps = v[0] * phs[0] + v[1] * phs[1] + v[2] * phs[2] + v[3] * phs[3];
            float pd = v[0] * phd[0] + v[1] * phd[1] + v[2] * phd[2] + v[3] * phd[3];
            #pragma unroll
            for (int off = 16; off; off >>= 1) {
                ps += __shfl_xor_sync(0xffffffffu, ps, off);
                pd += __shfl_xor_sync(0xffffffffu, pd, off);
            }
            if (tx == 0) { g_ssrc[row] = ps; g_sdst[row] = pd; }
        }
    }
}

// ---------------------------------------------------------------------------
// Kernel 2: fused per-row attention. One CTA (256 thr) per row.
//  Phase A (DRAM scan): 8 front-batched LDG.128(.cs) per thread; per 512B
//    chunk: integer nonzero tests -> 4 ballots -> ONE lane-0 atomicAdd ->
//    rank-ordered index writes to SMEM. No weight math inside the scan.
//  Phase B: bulk weight pass — independent g_sdst loads for all compacted
//    indices at once (latency overlapped), w = exp(lrelu(s)); no-max softmax
//    is exact (|s| << 88; softmax shift-invariant). One block sum.
//  Phase C: fp16 gather of x' rows (L2-resident), 8 ways x 32 lanes,
//    1/sum folded into the final float4 store.
// ---------------------------------------------------------------------------
__global__ void __launch_bounds__(256) gat_row_kernel(
    const float* __restrict__ adj, float* __restrict__ out)
{
    __shared__ int    s_idx[MAXNBR];    // 2 KB
    __shared__ float2 s_pair[MAXNBR];   // 4 KB: {bits(j), w}
    __shared__ float4 s_acc[256];       // 4 KB
    __shared__ float  s_w[12];
    __shared__ int    s_cnt;

    const int row  = blockIdx.x;
    const int tid  = threadIdx.x;
    const int lane = tid & 31;
    const int wid  = tid >> 5;

    const float s_i = g_ssrc[row];
    if (tid == 0) s_cnt = 1;            // slot 0 reserved for the self-loop
    __syncthreads();
    if (tid == 0) s_idx[0] = row;       // mask = adj + eye: self exactly once

    // ---- Phase A: front-batched scan + ballot compaction ----
    const uint4* arow = (const uint4*)(adj + (size_t)row * N_NODES);
    uint4 u[8];
    #pragma unroll
    for (int i = 0; i < 8; i++)
        u[i] = __ldcs(&arow[tid + i * 256]);

    const int row_g = row >> 2;
    #pragma unroll
    for (int i = 0; i < 8; i++) {
        const int g4 = tid + i * 256;
        uint4 v = u[i];
        if (g4 == row_g) {              // rare: zero self lane (pushed above)
            const int r3 = row & 3;
            v.x = (r3 == 0) ? 0u : v.x;
            v.y = (r3 == 1) ? 0u : v.y;
            v.z = (r3 == 2) ? 0u : v.z;
            v.w = (r3 == 3) ? 0u : v.w;
        }
        const bool h0 = v.x != 0u, h1 = v.y != 0u, h2 = v.z != 0u, h3 = v.w != 0u;
        const unsigned b0 = __ballot_sync(0xffffffffu, h0);
        const unsigned b1 = __ballot_sync(0xffffffffu, h1);
        const unsigned b2 = __ballot_sync(0xffffffffu, h2);
        const unsigned b3 = __ballot_sync(0xffffffffu, h3);
        const int c0 = __popc(b0), c1 = __popc(b1), c2 = __popc(b2), c3 = __popc(b3);
        const int tot = c0 + c1 + c2 + c3;
        if (tot) {                      // warp-uniform (ballot-derived)
            int base = 0;
            if (lane == 0) base = atomicAdd(&s_cnt, tot);
            base = __shfl_sync(0xffffffffu, base, 0);
            if (base + tot <= MAXNBR) {
                const unsigned ml = (1u << lane) - 1u;
                const int j0 = g4 * 4;
                if (h0) s_idx[base + __popc(b0 & ml)] = j0;
                if (h1) s_idx[base + c0 + __popc(b1 & ml)] = j0 + 1;
                if (h2) s_idx[base + c0 + c1 + __popc(b2 & ml)] = j0 + 2;
                if (h3) s_idx[base + c0 + c1 + c2 + __popc(b3 & ml)] = j0 + 3;
            }
        }
    }
    __syncthreads();
    const int cnt = min(s_cnt, MAXNBR);

    // ---- Phase B: bulk weights + denominator ----
    float sum = 0.0f;
    for (int k = tid; k < cnt; k += 256) {
        const int j = s_idx[k];
        float s = s_i + g_sdst[j];
        s = fmaxf(s, 0.2f * s);
        const float wv = __expf(s);
        s_pair[k] = make_float2(__int_as_float(j), wv);
        sum += wv;
    }
    #pragma unroll
    for (int off = 16; off; off >>= 1)
        sum += __shfl_xor_sync(0xffffffffu, sum, off);
    if (lane == 0) s_w[wid] = sum;
    __syncthreads();
    if (tid == 0) {
        float s = 0.0f;
        #pragma unroll
        for (int i = 0; i < 8; i++) s += s_w[i];
        s_w[8] = 1.0f / s;              // >= 1 term always (self-loop)
    }
    __syncthreads();
    const float inv = s_w[8];

    // ---- Phase C: fp16 weighted gather, 8 ways x 32 lanes ----
    const int way = wid;                         // neighbor way 0..7
    const uint2* xp2 = (const uint2*)g_xph;      // 32 uint2 per x' row
    float4 acc = make_float4(0.f, 0.f, 0.f, 0.f);

    int k = way;
    for (; k + 8 < cnt; k += 16) {
        const float2 p0 = s_pair[k];
        const float2 p1 = s_pair[k + 8];
        const uint2 v0 = xp2[(size_t)__float_as_int(p0.x) * 32 + lane];
        const uint2 v1 = xp2[(size_t)__float_as_int(p1.x) * 32 + lane];
        const float2 a0 = __half22float2(*(const __half2*)&v0.x);
        const float2 b0 = __half22float2(*(const __half2*)&v0.y);
        const float2 a1 = __half22float2(*(const __half2*)&v1.x);
        const float2 b1 = __half22float2(*(const __half2*)&v1.y);
        acc.x = fmaf(p0.y, a0.x, acc.x); acc.y = fmaf(p0.y, a0.y, acc.y);
        acc.z = fmaf(p0.y, b0.x, acc.z); acc.w = fmaf(p0.y, b0.y, acc.w);
        acc.x = fmaf(p1.y, a1.x, acc.x); acc.y = fmaf(p1.y, a1.y, acc.y);
        acc.z = fmaf(p1.y, b1.x, acc.z); acc.w = fmaf(p1.y, b1.y, acc.w);
    }
    for (; k < cnt; k += 8) {
        const float2 p0 = s_pair[k];
        const uint2 v0 = xp2[(size_t)__float_as_int(p0.x) * 32 + lane];
        const float2 a0 = __half22float2(*(const __half2*)&v0.x);
        const float2 b0 = __half22float2(*(const __half2*)&v0.y);
        acc.x = fmaf(p0.y, a0.x, acc.x); acc.y = fmaf(p0.y, a0.y, acc.y);
        acc.z = fmaf(p0.y, b0.x, acc.z); acc.w = fmaf(p0.y, b0.y, acc.w);
    }
    s_acc[tid] = acc;
    __syncthreads();

    if (tid < 128) {
        const float4 o = s_acc[tid + 128];
        acc = s_acc[tid];
        acc.x += o.x; acc.y += o.y; acc.z += o.z; acc.w += o.w;
        s_acc[tid] = acc;
    }
    __syncthreads();
    if (tid < 64) {
        const float4 o = s_acc[tid + 64];
        acc = s_acc[tid];
        acc.x += o.x; acc.y += o.y; acc.z += o.z; acc.w += o.w;
        s_acc[tid] = acc;
    }
    __syncthreads();
    if (tid < 32) {
        const float4 a = s_acc[tid];
        const float4 b = s_acc[tid + 32];
        float4 r;
        r.x = (a.x + b.x) * inv;
        r.y = (a.y + b.y) * inv;
        r.z = (a.z + b.z) * inv;
        r.w = (a.w + b.w) * inv;
        *(float4*)(out + (size_t)row * F_OUT + tid * 4) = r;
    }
}

// ---------------------------------------------------------------------------
extern "C" void kernel_launch(void* const* d_in, const int* in_sizes, int n_in,
                              void* d_out, int out_size)
{
    const float* adj  = (const float*)d_in[0];   // [8192, 8192]
    const float* x    = (const float*)d_in[1];   // [8192, 256]
    const float* w    = (const float*)d_in[2];   // [256, 128]
    const float* bias = (const float*)d_in[3];   // [128]
    const float* phi  = (const float*)d_in[4];   // [256, 1]
    float* out = (float*)d_out;                  // [8192, 128]

    gemm_xp_kernel<<<N_NODES / BM, 256>>>(x, w, bias, phi);
    gat_row_kernel<<<N_NODES, 256>>>(adj, out);
}

// round 13
// speedup vs baseline: 1.5119x; 1.2536x over previous
#include <cuda_runtime.h>
#include <cuda_fp16.h>
#include <math.h>

#define N_NODES 8192
#define F_IN    256
#define F_OUT   128
#define WSEG    64   // per-warp slots: warp scans 1024 elems, mean 10.3 hits, 16 sigma

// Scratch (device globals — allocation-free per harness rules)
__device__ __half g_xph[N_NODES * F_OUT];   // 2 MB fp16 x' (gather source)
__device__ float  g_ssrc[N_NODES];
__device__ float  g_sdst[N_NODES];

// ---------------------------------------------------------------------------
// f32x2 packed FMA (Blackwell FFMA2 — 2x fp32 FMA throughput)
// ---------------------------------------------------------------------------
__device__ __forceinline__ unsigned long long pack2(float a, float b) {
    unsigned long long r;
    asm("mov.b64 %0, {%1, %2};" : "=l"(r) : "f"(a), "f"(b));
    return r;
}
__device__ __forceinline__ unsigned long long fma2(
    unsigned long long a, unsigned long long b, unsigned long long c) {
    unsigned long long d;
    asm("fma.rn.f32x2 %0, %1, %2, %3;" : "=l"(d) : "l"(a), "l"(b), "l"(c));
    return d;
}
__device__ __forceinline__ void unpack2(unsigned long long v, float& a, float& b) {
    asm("mov.b64 {%0, %1}, %2;" : "=f"(a), "=f"(b) : "l"(v));
}

// ---------------------------------------------------------------------------
// Kernel 1: x' = x @ W + bias, fused scores s_src/s_dst = x' . phi.
// (R12 version, measured 20.3us.) BM=32 -> grid 256.
// ---------------------------------------------------------------------------
#define BM 32
#define BK 32
#define XS_LD 36

__global__ void __launch_bounds__(256) gemm_xp_kernel(
    const float* __restrict__ x, const float* __restrict__ w,
    const float* __restrict__ bias, const float* __restrict__ phi)
{
    __shared__ float xs[BK][XS_LD];   // transposed: xs[k][m]
    __shared__ float ws[BK][F_OUT];   // ws[k][n]

    const int tid  = threadIdx.x;
    const int tx   = tid & 31;
    const int ty   = tid >> 5;
    const int row0 = blockIdx.x * BM;

    unsigned long long acc[2][4];
    #pragma unroll
    for (int p = 0; p < 2; p++)
        #pragma unroll
        for (int j = 0; j < 4; j++) acc[p][j] = 0ull;

    for (int kt = 0; kt < F_IN; kt += BK) {
        {
            const int r = tid >> 3, c4 = tid & 7;
            const float4 v = *(const float4*)(x + (size_t)(row0 + r) * F_IN + kt + c4 * 4);
            xs[c4 * 4 + 0][r] = v.x;
            xs[c4 * 4 + 1][r] = v.y;
            xs[c4 * 4 + 2][r] = v.z;
            xs[c4 * 4 + 3][r] = v.w;
        }
        #pragma unroll
        for (int i = 0; i < 4; i++)
            ((float4*)ws)[tid + i * 256] =
                ((const float4*)(w + (size_t)kt * F_OUT))[tid + i * 256];
        __syncthreads();

        #pragma unroll 8
        for (int k = 0; k < BK; k++) {
            const ulonglong2 xa = *(const ulonglong2*)&xs[k][ty * 4];
            const float4 wv = *(const float4*)&ws[k][tx * 4];
            const unsigned long long xu[2] = {xa.x, xa.y};
            unsigned long long w2[4];
            w2[0] = pack2(wv.x, wv.x);
            w2[1] = pack2(wv.y, wv.y);
            w2[2] = pack2(wv.z, wv.z);
            w2[3] = pack2(wv.w, wv.w);
            #pragma unroll
            for (int p = 0; p < 2; p++)
                #pragma unroll
                for (int j = 0; j < 4; j++)
                    acc[p][j] = fma2(xu[p], w2[j], acc[p][j]);
        }
        __syncthreads();
    }

    float bch[4], phs[4], phd[4];
    #pragma unroll
    for (int j = 0; j < 4; j++) {
        const int c = tx * 4 + j;
        bch[j] = bias[c];
        phs[j] = phi[c];
        phd[j] = phi[F_OUT + c];
    }

    #pragma unroll
    for (int p = 0; p < 2; p++) {
        float v0[4], v1[4];
        #pragma unroll
        for (int j = 0; j < 4; j++) {
            unpack2(acc[p][j], v0[j], v1[j]);
            v0[j] += bch[j];
            v1[j] += bch[j];
        }
        #pragma unroll
        for (int e = 0; e < 2; e++) {
            const float* v = e ? v1 : v0;
            const int row = row0 + ty * 4 + 2 * p + e;
            __half2 h01 = __floats2half2_rn(v[0], v[1]);
            __half2 h23 = __floats2half2_rn(v[2], v[3]);
            uint2 st;
            st.x = reinterpret_cast<unsigned&>(h01);
            st.y = reinterpret_cast<unsigned&>(h23);
            *(uint2*)(g_xph + (size_t)row * F_OUT + tx * 4) = st;

            float ps = v[0] * phs[0] + v[1] * phs[1] + v[2] * phs[2] + v[3] * phs[3];
            float pd = v[0] * phd[0] + v[1] * phd[1] + v[2] * phd[2] + v[3] * phd[3];
            #pragma unroll
            for (int off = 16; off; off >>= 1) {
                ps += __shfl_xor_sync(0xffffffffu, ps, off);
                pd += __shfl_xor_sync(0xffffffffu, pd, off);
            }
            if (tx == 0) { g_ssrc[row] = ps; g_sdst[row] = pd; }
        }
    }
}

// ---------------------------------------------------------------------------
// Kernel 2: fused per-row attention, ZERO ATOMICS. One CTA (8 warps) per row.
//  Scan: warp w owns uint4 [w*256, w*256+256) of the adj row. Per 512B chunk:
//    integer nonzero tests -> 4 ballots -> rank-ordered writes into the
//    warp's PRIVATE segment; running count kept in a register (warp-uniform).
//    (R5-R12 used smem atomicAdd: ~83 same-address ATOMS/CTA x 32cyc at
//     ~55 CTAs/SM = ~73us of serialized atomic-pipe time = R5's exact dur.)
//  Phase B: per-warp bulk weights w = exp(lrelu(s_src+s_dst)) (no-max
//    softmax is exact: |s| << 88, softmax shift-invariant); partial sums
//    combined across 8 warps once.
//  Phase C: per-warp fp16 gather over its own segment (L2-resident x'),
//    self-loop term added once by warp 0; one float4 tree reduce; 1/sum
//    folded into the final store.
// ---------------------------------------------------------------------------
__global__ void __launch_bounds__(256) gat_row_kernel(
    const float* __restrict__ adj, float* __restrict__ out)
{
    __shared__ int    s_idxw[8][WSEG + 4];   // 2.1 KB per-warp index segments
    __shared__ float2 s_pair[8][WSEG + 4];   // 4.3 KB {bits(j), w}
    __shared__ float4 s_acc[256];            // 4 KB
    __shared__ float  s_red[12];

    const int row  = blockIdx.x;
    const int tid  = threadIdx.x;
    const int lane = tid & 31;
    const int wid  = tid >> 5;

    const float s_i = g_ssrc[row];
    const uint4* arow = (const uint4*)(adj + (size_t)row * N_NODES);
    const int row_g = row >> 2;
    int cnt = 0;                             // warp-uniform running count

    // ---- Phase A: scan + warp-private ballot compaction ----
    #pragma unroll
    for (int rnd = 0; rnd < 2; rnd++) {
        uint4 u[4];
        #pragma unroll
        for (int it = 0; it < 4; it++)
            u[it] = __ldcs(&arow[(wid * 8 + rnd * 4 + it) * 32 + lane]);
        #pragma unroll
        for (int it = 0; it < 4; it++) {
            const int g4 = (wid * 8 + rnd * 4 + it) * 32 + lane;
            uint4 v = u[it];
            if (g4 == row_g) {               // rare: self handled separately
                const int r3 = row & 3;
                v.x = (r3 == 0) ? 0u : v.x;
                v.y = (r3 == 1) ? 0u : v.y;
                v.z = (r3 == 2) ? 0u : v.z;
                v.w = (r3 == 3) ? 0u : v.w;
            }
            const unsigned b0 = __ballot_sync(0xffffffffu, v.x != 0u);
            const unsigned b1 = __ballot_sync(0xffffffffu, v.y != 0u);
            const unsigned b2 = __ballot_sync(0xffffffffu, v.z != 0u);
            const unsigned b3 = __ballot_sync(0xffffffffu, v.w != 0u);
            if (b0 | b1 | b2 | b3) {         // warp-uniform
                const int c0 = __popc(b0), c1 = __popc(b1), c2 = __popc(b2);
                const int tot = c0 + c1 + c2 + __popc(b3);
                if (cnt + tot <= WSEG) {
                    const unsigned ml = (1u << lane) - 1u;
                    const int j0 = g4 * 4;
                    if (v.x) s_idxw[wid][cnt + __popc(b0 & ml)] = j0;
                    if (v.y) s_idxw[wid][cnt + c0 + __popc(b1 & ml)] = j0 + 1;
                    if (v.z) s_idxw[wid][cnt + c0 + c1 + __popc(b2 & ml)] = j0 + 2;
                    if (v.w) s_idxw[wid][cnt + c0 + c1 + c2 + __popc(b3 & ml)] = j0 + 3;
                }
                cnt += tot;
            }
        }
    }
    if (cnt > WSEG) cnt = WSEG;
    __syncwarp();

    // ---- Phase B: per-warp bulk weights + block denominator ----
    float sum = 0.0f;
    for (int k = lane; k < cnt; k += 32) {
        const int j = s_idxw[wid][k];
        float s = s_i + g_sdst[j];
        s = fmaxf(s, 0.2f * s);
        const float wv = __expf(s);
        s_pair[wid][k] = make_float2(__int_as_float(j), wv);
        sum += wv;
    }
    #pragma unroll
    for (int off = 16; off; off >>= 1)
        sum += __shfl_xor_sync(0xffffffffu, sum, off);
    if (lane == 0) s_red[wid] = sum;
    __syncthreads();
    if (tid == 0) {
        float t = 0.0f;
        #pragma unroll
        for (int i = 0; i < 8; i++) t += s_red[i];
        float ss = s_i + g_sdst[row];        // self-loop (mask = adj + eye)
        ss = fmaxf(ss, 0.2f * ss);
        const float wself = __expf(ss);
        s_red[8] = 1.0f / (t + wself);       // >= 1 term always
        s_red[9] = wself;
    }
    __syncthreads();
    const float inv = s_red[8];

    // ---- Phase C: per-warp fp16 gather over own segment ----
    const uint2* xp2 = (const uint2*)g_xph;  // 32 uint2 per x' row
    float4 acc = make_float4(0.f, 0.f, 0.f, 0.f);
    if (wid == 0) {                          // self term exactly once
        const float wself = s_red[9];
        const uint2 vs = xp2[(size_t)row * 32 + lane];
        const float2 a = __half22float2(*(const __half2*)&vs.x);
        const float2 b = __half22float2(*(const __half2*)&vs.y);
        acc = make_float4(wself * a.x, wself * a.y, wself * b.x, wself * b.y);
    }

    int k = 0;
    for (; k + 2 <= cnt; k += 2) {
        const float2 p0 = s_pair[wid][k];
        const float2 p1 = s_pair[wid][k + 1];
        const uint2 v0 = xp2[(size_t)__float_as_int(p0.x) * 32 + lane];
        const uint2 v1 = xp2[(size_t)__float_as_int(p1.x) * 32 + lane];
        const float2 a0 = __half22float2(*(const __half2*)&v0.x);
        const float2 b0 = __half22float2(*(const __half2*)&v0.y);
        const float2 a1 = __half22float2(*(const __half2*)&v1.x);
        const float2 b1 = __half22float2(*(const __half2*)&v1.y);
        acc.x = fmaf(p0.y, a0.x, acc.x); acc.y = fmaf(p0.y, a0.y, acc.y);
        acc.z = fmaf(p0.y, b0.x, acc.z); acc.w = fmaf(p0.y, b0.y, acc.w);
        acc.x = fmaf(p1.y, a1.x, acc.x); acc.y = fmaf(p1.y, a1.y, acc.y);
        acc.z = fmaf(p1.y, b1.x, acc.z); acc.w = fmaf(p1.y, b1.y, acc.w);
    }
    if (k < cnt) {
        const float2 p0 = s_pair[wid][k];
        const uint2 v0 = xp2[(size_t)__float_as_int(p0.x) * 32 + lane];
        const float2 a0 = __half22float2(*(const __half2*)&v0.x);
        const float2 b0 = __half22float2(*(const __half2*)&v0.y);
        acc.x = fmaf(p0.y, a0.x, acc.x); acc.y = fmaf(p0.y, a0.y, acc.y);
        acc.z = fmaf(p0.y, b0.x, acc.z); acc.w = fmaf(p0.y, b0.y, acc.w);
    }
    s_acc[tid] = acc;
    __syncthreads();

    if (tid < 128) {
        const float4 o = s_acc[tid + 128];
        acc = s_acc[tid];
        acc.x += o.x; acc.y += o.y; acc.z += o.z; acc.w += o.w;
        s_acc[tid] = acc;
    }
    __syncthreads();
    if (tid < 64) {
        const float4 o = s_acc[tid + 64];
        acc = s_acc[tid];
        acc.x += o.x; acc.y += o.y; acc.z += o.z; acc.w += o.w;
        s_acc[tid] = acc;
    }
    __syncthreads();
    if (tid < 32) {
        const float4 a = s_acc[tid];
        const float4 b = s_acc[tid + 32];
        float4 r;
        r.x = (a.x + b.x) * inv;
        r.y = (a.y + b.y) * inv;
        r.z = (a.z + b.z) * inv;
        r.w = (a.w + b.w) * inv;
        *(float4*)(out + (size_t)row * F_OUT + tid * 4) = r;
    }
}

// ---------------------------------------------------------------------------
extern "C" void kernel_launch(void* const* d_in, const int* in_sizes, int n_in,
                              void* d_out, int out_size)
{
    const float* adj  = (const float*)d_in[0];   // [8192, 8192]
    const float* x    = (const float*)d_in[1];   // [8192, 256]
    const float* w    = (const float*)d_in[2];   // [256, 128]
    const float* bias = (const float*)d_in[3];   // [128]
    const float* phi  = (const float*)d_in[4];   // [256, 1]
    float* out = (float*)d_out;                  // [8192, 128]

    gemm_xp_kernel<<<N_NODES / BM, 256>>>(x, w, bias, phi);
    gat_row_kernel<<<N_NODES, 256>>>(adj, out);
}